// round 16
// baseline (speedup 1.0000x reference)
#include <cuda_runtime.h>

// Problem constants (fixed by the dataset instance)
#define W_ 256
#define PLANE 65536
#define THREADS 128
// tile = 8 patches (64c x 4r x 32w) -> 4096 tiles, one 128-thread block each.
// 4 blocks/SM (R15 win) + fused g2 algebra (deletes one full v-pass + 1 sync):
// g2 partials come from g1*S / g1*M computed in the g1 phase (g1>0, max commutes).

__device__ __forceinline__ float sigm(float x) {
    return 1.0f / (1.0f + __expf(-x));
}

__global__ __launch_bounds__(THREADS, 4)
void ciam_n4f_kernel(const float* __restrict__ x,
                     const float* __restrict__ fc_w,
                     const float* __restrict__ fc_b,
                     const float* __restrict__ c1w,
                     const float* __restrict__ c1b,
                     const float* __restrict__ c2w,
                     const float* __restrict__ c2b,
                     float* __restrict__ out)
{
    // ---- block / thread decomposition ----
    const int blk = blockIdx.x;          // 0..4095
    const int pwg = blk & 7;             // 8-patch group along W (32 px wide)
    const int ph  = (blk >> 3) & 63;     // patch row
    const int b   = blk >> 9;            // batch

    const int t  = threadIdx.x;          // 0..127
    const int p  = t & 7;                // patch
    const int r  = (t >> 3) & 3;         // row within patch
    const int cb = t >> 5;               // channel base 0..3 == warp id (c = cb + 4k)
    const int rp = t & 31;               // (r, patch)

    // ---- shared memory (~30.6 KB) ----
    __shared__ float wS[64 * 68];        // fc_w rows, stride 68
    __shared__ float fcbS[64];
    __shared__ float mxT[512];           // channel maxes [c][p] (p contiguous, 8 wide)
    __shared__ float msm[512];           // channel attention m[c][p]
    __shared__ float g1s[128];           // g1[(r,p)*4 + px]
    __shared__ float g2s[8];
    __shared__ float uni[2080];          // pm[4][520] -> gsum[512]+gmax[512]+p2s/p2m[256]

    // ---- scalar weights ----
    const float c1w0 = __ldg(c1w), c1w1 = __ldg(c1w + 1), c1b0 = __ldg(c1b);
    const float c2w0 = __ldg(c2w), c2w1 = __ldg(c2w + 1), c2b0 = __ldg(c2b);

    // ---- load tile into registers (16 x float4 / thread, coalesced) ----
    const size_t plane = PLANE;
    const float* xb = x + (size_t)b * 64 * plane;
    float* ob = out + (size_t)b * 64 * plane;
    const int rowbase = (ph * 4 + r) * W_ + pwg * 32 + p * 4;

    float4 v[16];
    #pragma unroll
    for (int k = 0; k < 16; k++)
        v[k] = *(const float4*)(xb + (size_t)(cb + 4 * k) * plane + rowbase);

    // ---- stage fc_w -> smem (stride 68), fc_b -> smem ----
    #pragma unroll
    for (int i = 0; i < 8; i++) {
        const int j  = t + 128 * i;      // float4 chunk id, 0..1023
        const int c  = j >> 4;
        const int k4 = j & 15;
        *(float4*)(wS + c * 68 + k4 * 4) = *(const float4*)(fc_w + c * 64 + k4 * 4);
    }
    if (t < 64) fcbS[t] = fc_b[t];

    // ---- phase 1: per-(c,r,p) row max -> pm (row stride 520, conflict-free) ----
    float* pm = uni;                     // [r][c*8+p]
    #pragma unroll
    for (int k = 0; k < 16; k++) {
        float4 a = v[k];
        pm[r * 520 + (cb + 4 * k) * 8 + p] =
            fmaxf(fmaxf(a.x, a.y), fmaxf(a.z, a.w));
    }
    __syncthreads();

    // ---- phase 2: reduce over r -> mxT (float4 form, 4 per thread) ----
    {
        const int id4 = t * 4;           // 0..508, covers c*8+p
        float4 a0 = *(const float4*)(pm + id4);
        float4 a1 = *(const float4*)(pm + 520 + id4);
        float4 a2 = *(const float4*)(pm + 1040 + id4);
        float4 a3 = *(const float4*)(pm + 1560 + id4);
        float4 mr;
        mr.x = fmaxf(fmaxf(a0.x, a1.x), fmaxf(a2.x, a3.x));
        mr.y = fmaxf(fmaxf(a0.y, a1.y), fmaxf(a2.y, a3.y));
        mr.z = fmaxf(fmaxf(a0.z, a1.z), fmaxf(a2.z, a3.z));
        mr.w = fmaxf(fmaxf(a0.w, a1.w), fmaxf(a2.w, a3.w));
        *(float4*)(mxT + id4) = mr;
    }
    __syncthreads();

    // ---- phase 3: matvec m[c][p] = sigm(w[c].mx[:,p] + b[c]); 4 outputs/thread ----
    {
        const int c   = t >> 1;          // 0..63
        const int pq4 = (t & 1) * 4;     // patches 0-3 or 4-7
        float4 acc = make_float4(0.f, 0.f, 0.f, 0.f);
        #pragma unroll
        for (int kc = 0; kc < 16; kc++) {
            const float4 w4 = *(const float4*)(wS + c * 68 + kc * 4);
            const float4 m0 = *(const float4*)(mxT + (kc * 4 + 0) * 8 + pq4);
            const float4 m1 = *(const float4*)(mxT + (kc * 4 + 1) * 8 + pq4);
            acc.x += w4.x * m0.x + w4.y * m1.x;
            acc.y += w4.x * m0.y + w4.y * m1.y;
            acc.z += w4.x * m0.z + w4.y * m1.z;
            acc.w += w4.x * m0.w + w4.y * m1.w;
            const float4 m2 = *(const float4*)(mxT + (kc * 4 + 2) * 8 + pq4);
            const float4 m3 = *(const float4*)(mxT + (kc * 4 + 3) * 8 + pq4);
            acc.x += w4.z * m2.x + w4.w * m3.x;
            acc.y += w4.z * m2.y + w4.w * m3.y;
            acc.z += w4.z * m2.z + w4.w * m3.z;
            acc.w += w4.z * m2.w + w4.w * m3.w;
        }
        const float bc = fcbS[c];
        float4 mres;
        mres.x = sigm(acc.x + bc);
        mres.y = sigm(acc.y + bc);
        mres.z = sigm(acc.z + bc);
        mres.w = sigm(acc.w + bc);
        *(float4*)(msm + c * 8 + pq4) = mres;
    }
    __syncthreads();

    // ---- phase 4: apply m; per-(patch,pixel) partials over this thread's 16 channels ----
    float4 ps  = make_float4(0.f, 0.f, 0.f, 0.f);
    float4 pmx = make_float4(-3.4e38f, -3.4e38f, -3.4e38f, -3.4e38f);
    #pragma unroll
    for (int k = 0; k < 16; k++) {
        const float m = msm[(cb + 4 * k) * 8 + p];
        v[k].x *= m; v[k].y *= m; v[k].z *= m; v[k].w *= m;
        ps.x += v[k].x; ps.y += v[k].y; ps.z += v[k].z; ps.w += v[k].w;
        pmx.x = fmaxf(pmx.x, v[k].x); pmx.y = fmaxf(pmx.y, v[k].y);
        pmx.z = fmaxf(pmx.z, v[k].z); pmx.w = fmaxf(pmx.w, v[k].w);
    }
    float* gsum = uni;                   // [cb][rp*4+px] : 512 floats
    float* gmax = uni + 512;
    *(float4*)(gsum + cb * 128 + rp * 4) = ps;
    *(float4*)(gmax + cb * 128 + rp * 4) = pmx;
    __syncthreads();

    // ---- phase 5: g1 per (patch,pixel) AND g2 partials (fused — no second v-pass) ----
    // S[px] = sum_c x*m, M[px] = max_c x*m -> g1 = sigm(...);
    // g2 contributions: sum-part = g1*S, max-part = g1*M (g1 > 0 so max commutes)
    float* p2s = uni + 1024;             // 128 floats, indexed by t = (r,p,px)
    float* p2m = uni + 1152;
    {
        float s  = gsum[t] + gsum[128 + t] + gsum[256 + t] + gsum[384 + t];
        float mx = fmaxf(fmaxf(gmax[t], gmax[128 + t]), fmaxf(gmax[256 + t], gmax[384 + t]));
        const float g1 = sigm(c1w0 * (s * (1.0f / 64.0f)) + c1w1 * mx + c1b0);
        g1s[t] = g1;
        p2s[t] = g1 * s;
        p2m[t] = g1 * mx;
    }
    __syncthreads();

    // ---- phase 6: g2 per patch (16 (r,px) contributions each) ----
    if (t < 8) {
        float s = 0.f, mx = -3.4e38f;
        #pragma unroll
        for (int rr = 0; rr < 4; rr++) {
            #pragma unroll
            for (int px = 0; px < 4; px++) {
                const int id = rr * 32 + t * 4 + px;
                s += p2s[id];
                mx = fmaxf(mx, p2m[id]);
            }
        }
        g2s[t] = sigm(c2w0 * (s * (1.0f / 1024.0f)) + c2w1 * mx + c2b0);
    }
    __syncthreads();

    // ---- phase 7: y = (x*m) * (g1*g2), single fused store pass ----
    const float4 g1v = *(const float4*)(g1s + rp * 4);
    const float g2 = g2s[p];
    const float4 gg = make_float4(g1v.x * g2, g1v.y * g2, g1v.z * g2, g1v.w * g2);
    #pragma unroll
    for (int k = 0; k < 16; k++) {
        float4 a = v[k];
        a.x *= gg.x; a.y *= gg.y; a.z *= gg.z; a.w *= gg.w;
        *(float4*)(ob + (size_t)(cb + 4 * k) * plane + rowbase) = a;
    }
}

extern "C" void kernel_launch(void* const* d_in, const int* in_sizes, int n_in,
                              void* d_out, int out_size) {
    const float* x    = (const float*)d_in[0];
    const float* fc_w = (const float*)d_in[1];
    const float* fc_b = (const float*)d_in[2];
    const float* c1w  = (const float*)d_in[3];
    const float* c1b  = (const float*)d_in[4];
    const float* c2w  = (const float*)d_in[5];
    const float* c2b  = (const float*)d_in[6];
    float* out = (float*)d_out;

    // 4096 blocks: 8 batches x 64 patch-rows x 8 groups of 8 patches
    ciam_n4f_kernel<<<4096, THREADS>>>(x, fc_w, fc_b, c1w, c1b, c2w, c2b, out);
}